// round 1
// baseline (speedup 1.0000x reference)
#include <cuda_runtime.h>
#include <cstdint>

#define N_DIS   20000
#define N_MIC   80000
#define N_NODES 100000
#define N_EDGES 1600000
#define F 64
#define SLOPE 0.2f

// ---- scratch (static device globals: allocation-free) ----
__device__ float    g_z[(size_t)N_NODES * F];   // projected features
__device__ float    g_e[N_EDGES];               // edge scores -> exp values
__device__ unsigned g_mkey[N_NODES];            // order-preserving float keys for max
__device__ float    g_den[N_NODES];             // softmax denom -> reciprocal
__device__ float    g_h[(size_t)N_NODES * F];   // accumulated output

// ---- packed f32x2 helpers ----
__device__ __forceinline__ unsigned long long pk2(float a, float b) {
    unsigned long long r;
    asm("mov.b64 %0, {%1, %2};" : "=l"(r) : "f"(a), "f"(b));
    return r;
}
__device__ __forceinline__ void upk2(unsigned long long v, float& a, float& b) {
    asm("mov.b64 {%0, %1}, %2;" : "=f"(a), "=f"(b) : "l"(v));
}
__device__ __forceinline__ void ffma2(unsigned long long& d, unsigned long long a, unsigned long long b) {
    asm("fma.rn.f32x2 %0, %1, %2, %0;" : "+l"(d) : "l"(a), "l"(b));
}

// ============================================================
// init: zero h, max-keys, denom
// ============================================================
__global__ void init_kernel() {
    int i = blockIdx.x * blockDim.x + threadIdx.x;
    if (i < N_NODES * F) g_h[i] = 0.f;
    if (i < N_NODES) { g_mkey[i] = 0u; g_den[i] = 0.f; }
}

// ============================================================
// GEMM: Z[row, 0..63] = X[row, :] @ W   (W staged in SMEM, f32x2 math)
// block = 256 threads, 64 rows per block.
// thread: rg = tid>>5 (row group), fp = tid&31 (feature pair 2fp,2fp+1)
// accumulates rows rg, rg+8, ..., rg+56.
// ============================================================
__global__ __launch_bounds__(256) void gemm_kernel(
    const float* __restrict__ X, const float* __restrict__ Wm,
    int R, int K, int K32, int zRowOffset)
{
    extern __shared__ float smem[];
    float* Ws = smem;                                              // K32*64 floats
    unsigned long long* Xs = (unsigned long long*)(smem + (size_t)K32 * 64); // 64*32 ull (x duplicated)

    int tid = threadIdx.x;
    // stage W, zero-padded to K32
    for (int i = tid; i < K32 * 64; i += 256)
        Ws[i] = (i < K * 64) ? Wm[i] : 0.f;

    int row0 = blockIdx.x * 64;
    int rg = tid >> 5;
    int fp = tid & 31;
    int c  = tid & 31;

    unsigned long long acc[8];
#pragma unroll
    for (int i = 0; i < 8; i++) acc[i] = 0ULL;

    for (int kb = 0; kb < K32; kb += 32) {
        __syncthreads();
        // stage X tile (64 rows x 32 k), each value duplicated into both f32x2 halves
        for (int rr = tid >> 5; rr < 64; rr += 8) {
            int grow = row0 + rr;
            int gk = kb + c;
            float v = (grow < R && gk < K) ? X[(size_t)grow * K + gk] : 0.f;
            Xs[rr * 32 + c] = pk2(v, v);
        }
        __syncthreads();
        const unsigned long long* Wp = (const unsigned long long*)(Ws + (size_t)kb * 64);
#pragma unroll 8
        for (int kk = 0; kk < 32; kk++) {
            unsigned long long w2 = Wp[kk * 32 + fp];
#pragma unroll
            for (int i = 0; i < 8; i++)
                ffma2(acc[i], Xs[(rg + 8 * i) * 32 + kk], w2);
        }
    }

#pragma unroll
    for (int i = 0; i < 8; i++) {
        int row = row0 + rg + 8 * i;
        if (row < R) {
            float a, b; upk2(acc[i], a, b);
            float2* zp = (float2*)(g_z + (size_t)(zRowOffset + row) * F + 2 * fp);
            *zp = make_float2(a, b);
        }
    }
}

// ============================================================
// edge pass 1: e = leaky_relu(dot(z[src], z[dst])), atomicMax m[dst]
// 16 lanes per edge (float4 each), 2 edges per warp
// ============================================================
__global__ __launch_bounds__(256) void edge_score_kernel(
    const int* __restrict__ src, const int* __restrict__ dst)
{
    int lane = threadIdx.x & 31;
    int half = lane >> 4;
    int l16  = lane & 15;
    int warp = (blockIdx.x * (blockDim.x >> 5)) + (threadIdx.x >> 5);
    int e = warp * 2 + half;
    if (e >= N_EDGES) return;

    int s = src[e], d = dst[e];
    const float4* zs = (const float4*)(g_z + (size_t)s * F);
    const float4* zd = (const float4*)(g_z + (size_t)d * F);
    float4 a = zs[l16], b = zd[l16];
    float p = a.x * b.x + a.y * b.y + a.z * b.z + a.w * b.w;
    p += __shfl_xor_sync(0xffffffffu, p, 8);
    p += __shfl_xor_sync(0xffffffffu, p, 4);
    p += __shfl_xor_sync(0xffffffffu, p, 2);
    p += __shfl_xor_sync(0xffffffffu, p, 1);
    if (l16 == 0) {
        float ev = (p >= 0.f) ? p : SLOPE * p;
        g_e[e] = ev;
        unsigned key = __float_as_uint(ev);
        key = (key & 0x80000000u) ? ~key : (key | 0x80000000u);
        atomicMax(&g_mkey[d], key);
    }
}

// ============================================================
// edge pass 2: e <- exp(e - m[dst]); denom[dst] += e
// ============================================================
__global__ __launch_bounds__(256) void edge_exp_kernel(const int* __restrict__ dst)
{
    int i = blockIdx.x * blockDim.x + threadIdx.x;
    if (i >= N_EDGES) return;
    int d = dst[i];
    unsigned key = g_mkey[d];
    unsigned bits = (key & 0x80000000u) ? (key & 0x7fffffffu) : ~key;
    float mv = __uint_as_float(bits);
    float ex = expf(g_e[i] - mv);
    g_e[i] = ex;
    atomicAdd(&g_den[d], ex);
}

// ============================================================
// denom -> reciprocal
// ============================================================
__global__ void rden_kernel() {
    int i = blockIdx.x * blockDim.x + threadIdx.x;
    if (i < N_NODES) {
        float d = g_den[i];
        g_den[i] = (d > 0.f) ? (1.f / d) : 0.f;
    }
}

// ============================================================
// edge pass 3: h[dst] += (e_exp * rden[dst]) * z[src]   (vector red)
// 16 lanes per edge, red.global.add.v4.f32
// ============================================================
__global__ __launch_bounds__(256) void edge_scatter_kernel(
    const int* __restrict__ src, const int* __restrict__ dst)
{
    int lane = threadIdx.x & 31;
    int half = lane >> 4;
    int l16  = lane & 15;
    int warp = (blockIdx.x * (blockDim.x >> 5)) + (threadIdx.x >> 5);
    int e = warp * 2 + half;
    if (e >= N_EDGES) return;

    int s = src[e], d = dst[e];
    float w = g_e[e] * g_den[d];          // broadcast loads across the 16 lanes
    const float4* zs = (const float4*)(g_z + (size_t)s * F);
    float4 a = zs[l16];
    float* hp = g_h + (size_t)d * F + l16 * 4;
    asm volatile("red.global.add.v4.f32 [%0], {%1, %2, %3, %4};"
                 :: "l"(hp), "f"(a.x * w), "f"(a.y * w), "f"(a.z * w), "f"(a.w * w)
                 : "memory");
}

// ============================================================
// finalize: out = elu(h)
// ============================================================
__global__ void finalize_kernel(float* __restrict__ out) {
    int i = blockIdx.x * blockDim.x + threadIdx.x;
    if (i < N_NODES * F) {
        float x = g_h[i];
        out[i] = (x > 0.f) ? x : expm1f(x);
    }
}

// ============================================================
extern "C" void kernel_launch(void* const* d_in, const int* in_sizes, int n_in,
                              void* d_out, int out_size) {
    const float* d_sim  = (const float*)d_in[0];
    const float* mi_sim = (const float*)d_in[1];
    const float* W_d    = (const float*)d_in[2];
    const float* W_mi   = (const float*)d_in[3];
    const int*   src    = (const int*)d_in[4];
    const int*   dst    = (const int*)d_in[5];
    float* out = (float*)d_out;

    // max dynamic smem for the larger GEMM (512*64*4 + 64*32*8 = 147456 B)
    cudaFuncSetAttribute(gemm_kernel, cudaFuncAttributeMaxDynamicSharedMemorySize, 149504);

    init_kernel<<<(N_NODES * F + 255) / 256, 256>>>();

    size_t smem_d = (size_t)384 * 64 * 4 + 64 * 32 * 8; // 114688
    size_t smem_m = (size_t)512 * 64 * 4 + 64 * 32 * 8; // 147456
    gemm_kernel<<<(N_DIS + 63) / 64, 256, smem_d>>>(d_sim,  W_d,  N_DIS, 383, 384, 0);
    gemm_kernel<<<(N_MIC + 63) / 64, 256, smem_m>>>(mi_sim, W_mi, N_MIC, 495, 512, N_DIS);

    edge_score_kernel<<<(N_EDGES + 15) / 16, 256>>>(src, dst);
    edge_exp_kernel<<<(N_EDGES + 255) / 256, 256>>>(dst);
    rden_kernel<<<(N_NODES + 255) / 256, 256>>>();
    edge_scatter_kernel<<<(N_EDGES + 15) / 16, 256>>>(src, dst);
    finalize_kernel<<<(N_NODES * F + 255) / 256, 256>>>(out);
}

// round 5
// speedup vs baseline: 1.7900x; 1.7900x over previous
#include <cuda_runtime.h>
#include <cstdint>

#define N_DIS   20000
#define N_MIC   80000
#define N_NODES 100000
#define N_EDGES 1600000
#define F 64
#define SLOPE 0.2f
#define KC 32

typedef unsigned long long ull;

// ---- scratch (static device globals: allocation-free) ----
__device__ float    g_z[(size_t)N_NODES * F];   // projected features
__device__ float    g_e[N_EDGES];               // edge scores -> exp values
__device__ unsigned g_mkey[N_NODES];            // order-preserving float keys for max
__device__ float    g_den[N_NODES];             // softmax denom -> reciprocal
__device__ float    g_h[(size_t)N_NODES * F];   // accumulated output

// ---- packed f32x2 helpers ----
__device__ __forceinline__ ull pk2(float a, float b) {
    ull r;
    asm("mov.b64 %0, {%1, %2};" : "=l"(r) : "f"(a), "f"(b));
    return r;
}
__device__ __forceinline__ void upk2(ull v, float& a, float& b) {
    asm("mov.b64 {%0, %1}, %2;" : "=f"(a), "=f"(b) : "l"(v));
}
__device__ __forceinline__ void ffma2(ull& d, ull a, ull b) {
    asm("fma.rn.f32x2 %0, %1, %2, %0;" : "+l"(d) : "l"(a), "l"(b));
}

// ============================================================
// init: zero h, max-keys, denom
// ============================================================
__global__ void init_kernel() {
    int i = blockIdx.x * blockDim.x + threadIdx.x;
    if (i < N_NODES * F) g_h[i] = 0.f;
    if (i < N_NODES) { g_mkey[i] = 0u; g_den[i] = 0.f; }
}

// ============================================================
// GEMM: Z[128 rows, 64] = X @ W, FFMA2, double-buffered smem
// block = 256 threads; thread = (rt = tid>>4 row slot, ft = tid&15 feature
// quad). Thread computes rows {rt + 16*i, i=0..7} x features [4ft, 4ft+4).
// Xs tile: [2][128][34] ull (value duplicated into both f32x2 halves;
// row stride 34 -> even (16B-aligned ull2) and bank-conflict-free).
// Ws tile: [2][32][32] ull (feature pairs packed).
// NOTE: Ws offsets are RELATIVE to the Ws base pointer (round-4 bug was
// double-adding WS_BASE here -> smem OOB -> illegal memory access).
// ============================================================
#define XS_STRIDE 34
#define XS_BUF_OFF(b)  ((size_t)(b) * 128 * XS_STRIDE)
#define WS_BASE        (2 * 128 * XS_STRIDE)
#define WS_OFF(b)      ((size_t)(b) * KC * 32)
#define GEMM_SMEM_BYTES ((2 * 128 * XS_STRIDE + 2 * KC * 32) * 8)

__global__ __launch_bounds__(256, 2) void gemm_kernel(
    const float* __restrict__ X, const float* __restrict__ Wm,
    int R, int K, int nchunks, int zRowOffset)
{
    extern __shared__ __align__(16) ull smem[];
    ull* Xs = smem;            // [2][128][XS_STRIDE]
    ull* Ws = smem + WS_BASE;  // [2][KC][32]

    int tid  = threadIdx.x;
    int w    = tid >> 5;
    int lane = tid & 31;
    int rt   = tid >> 4;
    int ft   = tid & 15;
    int row0 = blockIdx.x * 128;

    ull acc[8][2];
#pragma unroll
    for (int i = 0; i < 8; i++) { acc[i][0] = 0ULL; acc[i][1] = 0ULL; }

    // ---- stage chunk 0 ----
    {
        int kb = 0;
#pragma unroll
        for (int it = 0; it < 16; it++) {
            int row = w + 8 * it;
            int grow = row0 + row;
            int gk = kb + lane;
            float v = (grow < R && gk < K) ? X[(size_t)grow * K + gk] : 0.f;
            Xs[XS_BUF_OFF(0) + (size_t)row * XS_STRIDE + lane] = pk2(v, v);
        }
#pragma unroll
        for (int ii = 0; ii < 4; ii++) {
            int i = tid + 256 * ii;          // 0..1023
            int kk = i >> 5, p = i & 31;
            int gk = kb + kk;
            float2 v = (gk < K) ? *(const float2*)(Wm + (size_t)gk * 64 + 2 * p)
                                : make_float2(0.f, 0.f);
            Ws[WS_OFF(0) + (size_t)kk * 32 + p] = pk2(v.x, v.y);
        }
    }
    __syncthreads();

    int buf = 0;
    for (int c = 0; c < nchunks; c++) {
        // ---- prefetch chunk c+1 into buf^1 ----
        if (c + 1 < nchunks) {
            int kb = (c + 1) * KC;
            int nb = buf ^ 1;
#pragma unroll
            for (int it = 0; it < 16; it++) {
                int row = w + 8 * it;
                int grow = row0 + row;
                int gk = kb + lane;
                float v = (grow < R && gk < K) ? X[(size_t)grow * K + gk] : 0.f;
                Xs[XS_BUF_OFF(nb) + (size_t)row * XS_STRIDE + lane] = pk2(v, v);
            }
#pragma unroll
            for (int ii = 0; ii < 4; ii++) {
                int i = tid + 256 * ii;
                int kk = i >> 5, p = i & 31;
                int gk = kb + kk;
                float2 v = (gk < K) ? *(const float2*)(Wm + (size_t)gk * 64 + 2 * p)
                                    : make_float2(0.f, 0.f);
                Ws[WS_OFF(nb) + (size_t)kk * 32 + p] = pk2(v.x, v.y);
            }
        }

        // ---- compute on buf ----
        const ull* xb = Xs + XS_BUF_OFF(buf) + (size_t)rt * XS_STRIDE;
        const ull* wb = Ws + WS_OFF(buf) + 2 * ft;
#pragma unroll 4
        for (int kj = 0; kj < KC / 2; kj++) {
            ulonglong2 w0 = *(const ulonglong2*)(wb + (size_t)(2 * kj) * 32);
            ulonglong2 w1 = *(const ulonglong2*)(wb + (size_t)(2 * kj + 1) * 32);
#pragma unroll
            for (int i = 0; i < 8; i++) {
                ulonglong2 x2 = *(const ulonglong2*)(xb + (size_t)(16 * i) * XS_STRIDE + 2 * kj);
                ffma2(acc[i][0], x2.x, w0.x);
                ffma2(acc[i][1], x2.x, w0.y);
                ffma2(acc[i][0], x2.y, w1.x);
                ffma2(acc[i][1], x2.y, w1.y);
            }
        }
        __syncthreads();
        buf ^= 1;
    }

    // ---- write out ----
#pragma unroll
    for (int i = 0; i < 8; i++) {
        int grow = row0 + rt + 16 * i;
        if (grow < R) {
            float a, b, c2, d2;
            upk2(acc[i][0], a, b);
            upk2(acc[i][1], c2, d2);
            *(float4*)(g_z + (size_t)(zRowOffset + grow) * F + 4 * ft) =
                make_float4(a, b, c2, d2);
        }
    }
}

// ============================================================
// edge pass 1: e = leaky_relu(dot(z[src], z[dst])), atomicMax m[dst]
// 16 lanes per edge; each half-warp handles 2 edges with front-batched
// loads (2x MLP). N_EDGES % 32 == 0 -> exact grid.
// ============================================================
__global__ __launch_bounds__(256) void edge_score_kernel(
    const int* __restrict__ src, const int* __restrict__ dst)
{
    int lane = threadIdx.x & 31;
    int half = lane >> 4;
    int l16  = lane & 15;
    int warp = (blockIdx.x * (blockDim.x >> 5)) + (threadIdx.x >> 5);
    int e0 = warp * 4 + half * 2;   // edges e0, e0+1

    int s0 = src[e0],     d0 = dst[e0];
    int s1 = src[e0 + 1], d1 = dst[e0 + 1];
    float4 a0 = ((const float4*)(g_z + (size_t)s0 * F))[l16];
    float4 b0 = ((const float4*)(g_z + (size_t)d0 * F))[l16];
    float4 a1 = ((const float4*)(g_z + (size_t)s1 * F))[l16];
    float4 b1 = ((const float4*)(g_z + (size_t)d1 * F))[l16];

    float p0 = a0.x * b0.x + a0.y * b0.y + a0.z * b0.z + a0.w * b0.w;
    float p1 = a1.x * b1.x + a1.y * b1.y + a1.z * b1.z + a1.w * b1.w;
#pragma unroll
    for (int off = 8; off >= 1; off >>= 1) {
        p0 += __shfl_xor_sync(0xffffffffu, p0, off);
        p1 += __shfl_xor_sync(0xffffffffu, p1, off);
    }
    if (l16 == 0) {
        float v0 = (p0 >= 0.f) ? p0 : SLOPE * p0;
        float v1 = (p1 >= 0.f) ? p1 : SLOPE * p1;
        g_e[e0] = v0;
        g_e[e0 + 1] = v1;
        unsigned k0 = __float_as_uint(v0);
        k0 = (k0 & 0x80000000u) ? ~k0 : (k0 | 0x80000000u);
        unsigned k1 = __float_as_uint(v1);
        k1 = (k1 & 0x80000000u) ? ~k1 : (k1 | 0x80000000u);
        atomicMax(&g_mkey[d0], k0);
        atomicMax(&g_mkey[d1], k1);
    }
}

// ============================================================
// edge pass 2: e <- exp(e - m[dst]); denom[dst] += e
// ============================================================
__global__ __launch_bounds__(256) void edge_exp_kernel(const int* __restrict__ dst)
{
    int i = blockIdx.x * blockDim.x + threadIdx.x;
    if (i >= N_EDGES) return;
    int d = dst[i];
    unsigned key = g_mkey[d];
    unsigned bits = (key & 0x80000000u) ? (key & 0x7fffffffu) : ~key;
    float mv = __uint_as_float(bits);
    float ex = expf(g_e[i] - mv);
    g_e[i] = ex;
    atomicAdd(&g_den[d], ex);
}

// ============================================================
__global__ void rden_kernel() {
    int i = blockIdx.x * blockDim.x + threadIdx.x;
    if (i < N_NODES) {
        float d = g_den[i];
        g_den[i] = (d > 0.f) ? (1.f / d) : 0.f;
    }
}

// ============================================================
// edge pass 3: h[dst] += (e_exp * rden[dst]) * z[src]
// 2 edges per half-warp, batched loads, vector red
// ============================================================
__global__ __launch_bounds__(256) void edge_scatter_kernel(
    const int* __restrict__ src, const int* __restrict__ dst)
{
    int lane = threadIdx.x & 31;
    int half = lane >> 4;
    int l16  = lane & 15;
    int warp = (blockIdx.x * (blockDim.x >> 5)) + (threadIdx.x >> 5);
    int e0 = warp * 4 + half * 2;

    int s0 = src[e0],     d0 = dst[e0];
    int s1 = src[e0 + 1], d1 = dst[e0 + 1];
    float w0 = g_e[e0] * g_den[d0];
    float w1 = g_e[e0 + 1] * g_den[d1];
    float4 a0 = ((const float4*)(g_z + (size_t)s0 * F))[l16];
    float4 a1 = ((const float4*)(g_z + (size_t)s1 * F))[l16];

    float* hp0 = g_h + (size_t)d0 * F + l16 * 4;
    float* hp1 = g_h + (size_t)d1 * F + l16 * 4;
    asm volatile("red.global.add.v4.f32 [%0], {%1, %2, %3, %4};"
                 :: "l"(hp0), "f"(a0.x * w0), "f"(a0.y * w0), "f"(a0.z * w0), "f"(a0.w * w0)
                 : "memory");
    asm volatile("red.global.add.v4.f32 [%0], {%1, %2, %3, %4};"
                 :: "l"(hp1), "f"(a1.x * w1), "f"(a1.y * w1), "f"(a1.z * w1), "f"(a1.w * w1)
                 : "memory");
}

// ============================================================
__global__ void finalize_kernel(float* __restrict__ out) {
    int i = blockIdx.x * blockDim.x + threadIdx.x;
    if (i < N_NODES * F) {
        float x = g_h[i];
        out[i] = (x > 0.f) ? x : expm1f(x);
    }
}

// ============================================================
extern "C" void kernel_launch(void* const* d_in, const int* in_sizes, int n_in,
                              void* d_out, int out_size) {
    const float* d_sim  = (const float*)d_in[0];
    const float* mi_sim = (const float*)d_in[1];
    const float* W_d    = (const float*)d_in[2];
    const float* W_mi   = (const float*)d_in[3];
    const int*   src    = (const int*)d_in[4];
    const int*   dst    = (const int*)d_in[5];
    float* out = (float*)d_out;

    cudaFuncSetAttribute(gemm_kernel, cudaFuncAttributeMaxDynamicSharedMemorySize,
                         GEMM_SMEM_BYTES);

    init_kernel<<<(N_NODES * F + 255) / 256, 256>>>();

    gemm_kernel<<<(N_DIS + 127) / 128, 256, GEMM_SMEM_BYTES>>>(
        d_sim, W_d, N_DIS, 383, (383 + KC - 1) / KC, 0);
    gemm_kernel<<<(N_MIC + 127) / 128, 256, GEMM_SMEM_BYTES>>>(
        mi_sim, W_mi, N_MIC, 495, (495 + KC - 1) / KC, N_DIS);

    // 4 edges per warp, 8 warps per block -> 32 edges per block
    edge_score_kernel<<<N_EDGES / 32, 256>>>(src, dst);
    edge_exp_kernel<<<(N_EDGES + 255) / 256, 256>>>(dst);
    rden_kernel<<<(N_NODES + 255) / 256, 256>>>();
    edge_scatter_kernel<<<N_EDGES / 32, 256>>>(src, dst);
    finalize_kernel<<<(N_NODES * F + 255) / 256, 256>>>(out);
}

// round 6
// speedup vs baseline: 1.8163x; 1.0147x over previous
#include <cuda_runtime.h>
#include <cstdint>

#define N_DIS   20000
#define N_MIC   80000
#define N_NODES 100000
#define N_EDGES 1600000
#define F 64
#define SLOPE 0.2f
#define KC 32

typedef unsigned long long ull;

// ---- scratch (static device globals: allocation-free) ----
__device__ float    g_z[(size_t)N_NODES * F];   // projected features
__device__ float    g_e[N_EDGES];               // edge scores (leaky_relu)
__device__ unsigned g_mkey[N_NODES];            // order-preserving float keys for max
__device__ float    g_den[N_NODES];             // softmax denom -> reciprocal
__device__ float    g_h[(size_t)N_NODES * F];   // accumulated (unnormalized) output

// ---- packed f32x2 helpers ----
__device__ __forceinline__ ull pk2(float a, float b) {
    ull r;
    asm("mov.b64 %0, {%1, %2};" : "=l"(r) : "f"(a), "f"(b));
    return r;
}
__device__ __forceinline__ void upk2(ull v, float& a, float& b) {
    asm("mov.b64 {%0, %1}, %2;" : "=f"(a), "=f"(b) : "l"(v));
}
__device__ __forceinline__ void ffma2(ull& d, ull a, ull b) {
    asm("fma.rn.f32x2 %0, %1, %2, %0;" : "+l"(d) : "l"(a), "l"(b));
}

// ============================================================
// init: zero h, max-keys, denom
// ============================================================
__global__ void init_kernel() {
    int i = blockIdx.x * blockDim.x + threadIdx.x;
    if (i < N_NODES * F) g_h[i] = 0.f;
    if (i < N_NODES) { g_mkey[i] = 0u; g_den[i] = 0.f; }
}

// ============================================================
// GEMM: Z[128 rows, 64] = X @ W, FFMA2, double-buffered smem
// ============================================================
#define XS_STRIDE 34
#define XS_BUF_OFF(b)  ((size_t)(b) * 128 * XS_STRIDE)
#define WS_BASE        (2 * 128 * XS_STRIDE)
#define WS_OFF(b)      ((size_t)(b) * KC * 32)
#define GEMM_SMEM_BYTES ((2 * 128 * XS_STRIDE + 2 * KC * 32) * 8)

__global__ __launch_bounds__(256, 2) void gemm_kernel(
    const float* __restrict__ X, const float* __restrict__ Wm,
    int R, int K, int nchunks, int zRowOffset)
{
    extern __shared__ __align__(16) ull smem[];
    ull* Xs = smem;            // [2][128][XS_STRIDE]
    ull* Ws = smem + WS_BASE;  // [2][KC][32]

    int tid  = threadIdx.x;
    int w    = tid >> 5;
    int lane = tid & 31;
    int rt   = tid >> 4;
    int ft   = tid & 15;
    int row0 = blockIdx.x * 128;

    ull acc[8][2];
#pragma unroll
    for (int i = 0; i < 8; i++) { acc[i][0] = 0ULL; acc[i][1] = 0ULL; }

    // ---- stage chunk 0 ----
    {
        int kb = 0;
#pragma unroll
        for (int it = 0; it < 16; it++) {
            int row = w + 8 * it;
            int grow = row0 + row;
            int gk = kb + lane;
            float v = (grow < R && gk < K) ? X[(size_t)grow * K + gk] : 0.f;
            Xs[XS_BUF_OFF(0) + (size_t)row * XS_STRIDE + lane] = pk2(v, v);
        }
#pragma unroll
        for (int ii = 0; ii < 4; ii++) {
            int i = tid + 256 * ii;          // 0..1023
            int kk = i >> 5, p = i & 31;
            int gk = kb + kk;
            float2 v = (gk < K) ? *(const float2*)(Wm + (size_t)gk * 64 + 2 * p)
                                : make_float2(0.f, 0.f);
            Ws[WS_OFF(0) + (size_t)kk * 32 + p] = pk2(v.x, v.y);
        }
    }
    __syncthreads();

    int buf = 0;
    for (int c = 0; c < nchunks; c++) {
        // ---- prefetch chunk c+1 into buf^1 ----
        if (c + 1 < nchunks) {
            int kb = (c + 1) * KC;
            int nb = buf ^ 1;
#pragma unroll
            for (int it = 0; it < 16; it++) {
                int row = w + 8 * it;
                int grow = row0 + row;
                int gk = kb + lane;
                float v = (grow < R && gk < K) ? X[(size_t)grow * K + gk] : 0.f;
                Xs[XS_BUF_OFF(nb) + (size_t)row * XS_STRIDE + lane] = pk2(v, v);
            }
#pragma unroll
            for (int ii = 0; ii < 4; ii++) {
                int i = tid + 256 * ii;
                int kk = i >> 5, p = i & 31;
                int gk = kb + kk;
                float2 v = (gk < K) ? *(const float2*)(Wm + (size_t)gk * 64 + 2 * p)
                                    : make_float2(0.f, 0.f);
                Ws[WS_OFF(nb) + (size_t)kk * 32 + p] = pk2(v.x, v.y);
            }
        }

        // ---- compute on buf ----
        const ull* xb = Xs + XS_BUF_OFF(buf) + (size_t)rt * XS_STRIDE;
        const ull* wb = Ws + WS_OFF(buf) + 2 * ft;
#pragma unroll 4
        for (int kj = 0; kj < KC / 2; kj++) {
            ulonglong2 w0 = *(const ulonglong2*)(wb + (size_t)(2 * kj) * 32);
            ulonglong2 w1 = *(const ulonglong2*)(wb + (size_t)(2 * kj + 1) * 32);
#pragma unroll
            for (int i = 0; i < 8; i++) {
                ulonglong2 x2 = *(const ulonglong2*)(xb + (size_t)(16 * i) * XS_STRIDE + 2 * kj);
                ffma2(acc[i][0], x2.x, w0.x);
                ffma2(acc[i][1], x2.x, w0.y);
                ffma2(acc[i][0], x2.y, w1.x);
                ffma2(acc[i][1], x2.y, w1.y);
            }
        }
        __syncthreads();
        buf ^= 1;
    }

    // ---- write out ----
#pragma unroll
    for (int i = 0; i < 8; i++) {
        int grow = row0 + rt + 16 * i;
        if (grow < R) {
            float a, b, c2, d2;
            upk2(acc[i][0], a, b);
            upk2(acc[i][1], c2, d2);
            *(float4*)(g_z + (size_t)(zRowOffset + grow) * F + 4 * ft) =
                make_float4(a, b, c2, d2);
        }
    }
}

// ============================================================
// edge pass 1: e = leaky_relu(dot(z[src], z[dst])), atomicMax m[dst]
// 4 edges per half-warp, front-batched gathers (4x MLP).
// ============================================================
__global__ __launch_bounds__(256) void edge_score_kernel(
    const int* __restrict__ src, const int* __restrict__ dst)
{
    int lane = threadIdx.x & 31;
    int half = lane >> 4;
    int l16  = lane & 15;
    int warp = (blockIdx.x * (blockDim.x >> 5)) + (threadIdx.x >> 5);
    int e0 = warp * 8 + half * 4;   // edges e0..e0+3

    int4 s = *(const int4*)(src + e0);
    int4 d = *(const int4*)(dst + e0);

    float4 a0 = ((const float4*)(g_z + (size_t)s.x * F))[l16];
    float4 b0 = ((const float4*)(g_z + (size_t)d.x * F))[l16];
    float4 a1 = ((const float4*)(g_z + (size_t)s.y * F))[l16];
    float4 b1 = ((const float4*)(g_z + (size_t)d.y * F))[l16];
    float4 a2 = ((const float4*)(g_z + (size_t)s.z * F))[l16];
    float4 b2 = ((const float4*)(g_z + (size_t)d.z * F))[l16];
    float4 a3 = ((const float4*)(g_z + (size_t)s.w * F))[l16];
    float4 b3 = ((const float4*)(g_z + (size_t)d.w * F))[l16];

    float p0 = a0.x * b0.x + a0.y * b0.y + a0.z * b0.z + a0.w * b0.w;
    float p1 = a1.x * b1.x + a1.y * b1.y + a1.z * b1.z + a1.w * b1.w;
    float p2 = a2.x * b2.x + a2.y * b2.y + a2.z * b2.z + a2.w * b2.w;
    float p3 = a3.x * b3.x + a3.y * b3.y + a3.z * b3.z + a3.w * b3.w;
#pragma unroll
    for (int off = 8; off >= 1; off >>= 1) {
        p0 += __shfl_xor_sync(0xffffffffu, p0, off);
        p1 += __shfl_xor_sync(0xffffffffu, p1, off);
        p2 += __shfl_xor_sync(0xffffffffu, p2, off);
        p3 += __shfl_xor_sync(0xffffffffu, p3, off);
    }
    if (l16 == 0) {
        float v0 = (p0 >= 0.f) ? p0 : SLOPE * p0;
        float v1 = (p1 >= 0.f) ? p1 : SLOPE * p1;
        float v2 = (p2 >= 0.f) ? p2 : SLOPE * p2;
        float v3 = (p3 >= 0.f) ? p3 : SLOPE * p3;
        *(float4*)(g_e + e0) = make_float4(v0, v1, v2, v3);
        unsigned k0 = __float_as_uint(v0); k0 = (k0 & 0x80000000u) ? ~k0 : (k0 | 0x80000000u);
        unsigned k1 = __float_as_uint(v1); k1 = (k1 & 0x80000000u) ? ~k1 : (k1 | 0x80000000u);
        unsigned k2 = __float_as_uint(v2); k2 = (k2 & 0x80000000u) ? ~k2 : (k2 | 0x80000000u);
        unsigned k3 = __float_as_uint(v3); k3 = (k3 & 0x80000000u) ? ~k3 : (k3 | 0x80000000u);
        atomicMax(&g_mkey[d.x], k0);
        atomicMax(&g_mkey[d.y], k1);
        atomicMax(&g_mkey[d.z], k2);
        atomicMax(&g_mkey[d.w], k3);
    }
}

// ============================================================
// edge pass 2 (FUSED exp + scatter, deferred normalization):
//   ex = exp(e - m[dst]);  den[dst] += ex;  h[dst] += ex * z[src]
// 4 edges per half-warp; exp computed once per edge on lane l16==0,
// broadcast via shfl (avoids 16x redundant MUFU).
// ============================================================
__global__ __launch_bounds__(256) void edge_accum_kernel(
    const int* __restrict__ src, const int* __restrict__ dst)
{
    int lane = threadIdx.x & 31;
    int half = lane >> 4;
    int l16  = lane & 15;
    int warp = (blockIdx.x * (blockDim.x >> 5)) + (threadIdx.x >> 5);
    int e0 = warp * 8 + half * 4;

    int4 s = *(const int4*)(src + e0);
    int4 d = *(const int4*)(dst + e0);

    float4 a0 = ((const float4*)(g_z + (size_t)s.x * F))[l16];
    float4 a1 = ((const float4*)(g_z + (size_t)s.y * F))[l16];
    float4 a2 = ((const float4*)(g_z + (size_t)s.z * F))[l16];
    float4 a3 = ((const float4*)(g_z + (size_t)s.w * F))[l16];

    float ex0 = 0.f, ex1 = 0.f, ex2 = 0.f, ex3 = 0.f;
    if (l16 == 0) {
        float4 ge = *(const float4*)(g_e + e0);
        unsigned k0 = g_mkey[d.x], k1 = g_mkey[d.y], k2 = g_mkey[d.z], k3 = g_mkey[d.w];
        float m0 = __uint_as_float((k0 & 0x80000000u) ? (k0 & 0x7fffffffu) : ~k0);
        float m1 = __uint_as_float((k1 & 0x80000000u) ? (k1 & 0x7fffffffu) : ~k1);
        float m2 = __uint_as_float((k2 & 0x80000000u) ? (k2 & 0x7fffffffu) : ~k2);
        float m3 = __uint_as_float((k3 & 0x80000000u) ? (k3 & 0x7fffffffu) : ~k3);
        ex0 = expf(ge.x - m0);
        ex1 = expf(ge.y - m1);
        ex2 = expf(ge.z - m2);
        ex3 = expf(ge.w - m3);
        atomicAdd(&g_den[d.x], ex0);
        atomicAdd(&g_den[d.y], ex1);
        atomicAdd(&g_den[d.z], ex2);
        atomicAdd(&g_den[d.w], ex3);
    }
    int srcLane = half << 4;
    ex0 = __shfl_sync(0xffffffffu, ex0, srcLane);
    ex1 = __shfl_sync(0xffffffffu, ex1, srcLane);
    ex2 = __shfl_sync(0xffffffffu, ex2, srcLane);
    ex3 = __shfl_sync(0xffffffffu, ex3, srcLane);

    float* hp0 = g_h + (size_t)d.x * F + l16 * 4;
    float* hp1 = g_h + (size_t)d.y * F + l16 * 4;
    float* hp2 = g_h + (size_t)d.z * F + l16 * 4;
    float* hp3 = g_h + (size_t)d.w * F + l16 * 4;
    asm volatile("red.global.add.v4.f32 [%0], {%1, %2, %3, %4};"
                 :: "l"(hp0), "f"(a0.x * ex0), "f"(a0.y * ex0), "f"(a0.z * ex0), "f"(a0.w * ex0) : "memory");
    asm volatile("red.global.add.v4.f32 [%0], {%1, %2, %3, %4};"
                 :: "l"(hp1), "f"(a1.x * ex1), "f"(a1.y * ex1), "f"(a1.z * ex1), "f"(a1.w * ex1) : "memory");
    asm volatile("red.global.add.v4.f32 [%0], {%1, %2, %3, %4};"
                 :: "l"(hp2), "f"(a2.x * ex2), "f"(a2.y * ex2), "f"(a2.z * ex2), "f"(a2.w * ex2) : "memory");
    asm volatile("red.global.add.v4.f32 [%0], {%1, %2, %3, %4};"
                 :: "l"(hp3), "f"(a3.x * ex3), "f"(a3.y * ex3), "f"(a3.z * ex3), "f"(a3.w * ex3) : "memory");
}

// ============================================================
// denom -> reciprocal (0 for empty nodes)
// ============================================================
__global__ void rden_kernel() {
    int i = blockIdx.x * blockDim.x + threadIdx.x;
    if (i < N_NODES) {
        float d = g_den[i];
        g_den[i] = (d > 0.f) ? (1.f / d) : 0.f;
    }
}

// ============================================================
// finalize: out = elu(h * rden[node])
// ============================================================
__global__ void finalize_kernel(float* __restrict__ out) {
    int i = blockIdx.x * blockDim.x + threadIdx.x;
    if (i < N_NODES * F) {
        float x = g_h[i] * g_den[i >> 6];
        out[i] = (x > 0.f) ? x : expm1f(x);
    }
}

// ============================================================
extern "C" void kernel_launch(void* const* d_in, const int* in_sizes, int n_in,
                              void* d_out, int out_size) {
    const float* d_sim  = (const float*)d_in[0];
    const float* mi_sim = (const float*)d_in[1];
    const float* W_d    = (const float*)d_in[2];
    const float* W_mi   = (const float*)d_in[3];
    const int*   src    = (const int*)d_in[4];
    const int*   dst    = (const int*)d_in[5];
    float* out = (float*)d_out;

    cudaFuncSetAttribute(gemm_kernel, cudaFuncAttributeMaxDynamicSharedMemorySize,
                         GEMM_SMEM_BYTES);

    init_kernel<<<(N_NODES * F + 255) / 256, 256>>>();

    gemm_kernel<<<(N_DIS + 127) / 128, 256, GEMM_SMEM_BYTES>>>(
        d_sim, W_d, N_DIS, 383, (383 + KC - 1) / KC, 0);
    gemm_kernel<<<(N_MIC + 127) / 128, 256, GEMM_SMEM_BYTES>>>(
        mi_sim, W_mi, N_MIC, 495, (495 + KC - 1) / KC, N_DIS);

    // 8 edges per warp, 8 warps per block -> 64 edges per block
    edge_score_kernel<<<N_EDGES / 64, 256>>>(src, dst);
    edge_accum_kernel<<<N_EDGES / 64, 256>>>(src, dst);
    rden_kernel<<<(N_NODES + 255) / 256, 256>>>();
    finalize_kernel<<<(N_NODES * F + 255) / 256, 256>>>(out);
}

// round 9
// speedup vs baseline: 1.9868x; 1.0939x over previous
#include <cuda_runtime.h>
#include <cstdint>

#define N_DIS   20000
#define N_MIC   80000
#define N_NODES 100000
#define N_EDGES 1600000
#define F 64
#define SLOPE 0.2f
#define KC 32

#define NB_D ((N_DIS + 127) / 128)   // 157
#define NB_M ((N_MIC + 127) / 128)   // 625

typedef unsigned long long ull;

// ---- scratch (static device globals: allocation-free) ----
__device__ float    g_z[(size_t)N_NODES * F];   // projected features
__device__ float    g_e[N_EDGES];               // edge scores (leaky_relu)
__device__ unsigned g_mkey[N_NODES];            // order-preserving float keys for max
__device__ float    g_den[N_NODES];             // softmax denom -> reciprocal
__device__ float    g_h[(size_t)N_NODES * F];   // accumulated (unnormalized) output

// ---- packed f32x2 helpers ----
__device__ __forceinline__ ull pk2(float a, float b) {
    ull r;
    asm("mov.b64 %0, {%1, %2};" : "=l"(r) : "f"(a), "f"(b));
    return r;
}
__device__ __forceinline__ void upk2(ull v, float& a, float& b) {
    asm("mov.b64 {%0, %1}, %2;" : "=f"(a), "=f"(b) : "l"(v));
}
__device__ __forceinline__ void ffma2(ull& d, ull a, ull b) {
    asm("fma.rn.f32x2 %0, %1, %2, %0;" : "+l"(d) : "l"(a), "l"(b));
}

// ============================================================
// init: zero h, max-keys, denom
// ============================================================
__global__ void init_kernel() {
    int i = blockIdx.x * blockDim.x + threadIdx.x;
    if (i < N_NODES * F) g_h[i] = 0.f;
    if (i < N_NODES) { g_mkey[i] = 0u; g_den[i] = 0.f; }
}

// ============================================================
// MERGED GEMM: one launch covers both projections.
// blocks [0, NB_D): d_sim @ W_d ; blocks [NB_D, NB_D+NB_M): mi_sim @ W_mi
// FFMA2, 8 rows x 4 features per thread, double-buffered smem.
// ============================================================
#define XS_STRIDE 34
#define XS_BUF_OFF(b)  ((size_t)(b) * 128 * XS_STRIDE)
#define WS_BASE        (2 * 128 * XS_STRIDE)
#define WS_OFF(b)      ((size_t)(b) * KC * 32)
#define GEMM_SMEM_BYTES ((2 * 128 * XS_STRIDE + 2 * KC * 32) * 8)

__global__ __launch_bounds__(256, 2) void gemm_kernel(
    const float* __restrict__ Xd, const float* __restrict__ Wd,
    const float* __restrict__ Xm, const float* __restrict__ Wm)
{
    extern __shared__ __align__(16) ull smem[];
    ull* Xs = smem;            // [2][128][XS_STRIDE]
    ull* Ws = smem + WS_BASE;  // [2][KC][32]

    const float* X;
    const float* Wmat;
    int R, K, nchunks, row0, zRowOffset;
    if (blockIdx.x < NB_D) {
        X = Xd; Wmat = Wd; R = N_DIS; K = 383; nchunks = (383 + KC - 1) / KC;
        row0 = blockIdx.x * 128; zRowOffset = 0;
    } else {
        X = Xm; Wmat = Wm; R = N_MIC; K = 495; nchunks = (495 + KC - 1) / KC;
        row0 = (blockIdx.x - NB_D) * 128; zRowOffset = N_DIS;
    }

    int tid  = threadIdx.x;
    int w    = tid >> 5;
    int lane = tid & 31;
    int rt   = tid >> 4;
    int ft   = tid & 15;

    ull acc[8][2];
#pragma unroll
    for (int i = 0; i < 8; i++) { acc[i][0] = 0ULL; acc[i][1] = 0ULL; }

    // ---- stage chunk 0 ----
    {
        int kb = 0;
#pragma unroll
        for (int it = 0; it < 16; it++) {
            int row = w + 8 * it;
            int grow = row0 + row;
            int gk = kb + lane;
            float v = (grow < R && gk < K) ? X[(size_t)grow * K + gk] : 0.f;
            Xs[XS_BUF_OFF(0) + (size_t)row * XS_STRIDE + lane] = pk2(v, v);
        }
#pragma unroll
        for (int ii = 0; ii < 4; ii++) {
            int i = tid + 256 * ii;          // 0..1023
            int kk = i >> 5, p = i & 31;
            int gk = kb + kk;
            float2 v = (gk < K) ? *(const float2*)(Wmat + (size_t)gk * 64 + 2 * p)
                                : make_float2(0.f, 0.f);
            Ws[WS_OFF(0) + (size_t)kk * 32 + p] = pk2(v.x, v.y);
        }
    }
    __syncthreads();

    int buf = 0;
    for (int c = 0; c < nchunks; c++) {
        // ---- prefetch chunk c+1 into buf^1 ----
        if (c + 1 < nchunks) {
            int kb = (c + 1) * KC;
            int nb = buf ^ 1;
#pragma unroll
            for (int it = 0; it < 16; it++) {
                int row = w + 8 * it;
                int grow = row0 + row;
                int gk = kb + lane;
                float v = (grow < R && gk < K) ? X[(size_t)grow * K + gk] : 0.f;
                Xs[XS_BUF_OFF(nb) + (size_t)row * XS_STRIDE + lane] = pk2(v, v);
            }
#pragma unroll
            for (int ii = 0; ii < 4; ii++) {
                int i = tid + 256 * ii;
                int kk = i >> 5, p = i & 31;
                int gk = kb + kk;
                float2 v = (gk < K) ? *(const float2*)(Wmat + (size_t)gk * 64 + 2 * p)
                                    : make_float2(0.f, 0.f);
                Ws[WS_OFF(nb) + (size_t)kk * 32 + p] = pk2(v.x, v.y);
            }
        }

        // ---- compute on buf ----
        const ull* xb = Xs + XS_BUF_OFF(buf) + (size_t)rt * XS_STRIDE;
        const ull* wb = Ws + WS_OFF(buf) + 2 * ft;
#pragma unroll
        for (int kj = 0; kj < KC / 2; kj++) {
            ulonglong2 w0 = *(const ulonglong2*)(wb + (size_t)(2 * kj) * 32);
            ulonglong2 w1 = *(const ulonglong2*)(wb + (size_t)(2 * kj + 1) * 32);
#pragma unroll
            for (int i = 0; i < 8; i++) {
                ulonglong2 x2 = *(const ulonglong2*)(xb + (size_t)(16 * i) * XS_STRIDE + 2 * kj);
                ffma2(acc[i][0], x2.x, w0.x);
                ffma2(acc[i][1], x2.x, w0.y);
                ffma2(acc[i][0], x2.y, w1.x);
                ffma2(acc[i][1], x2.y, w1.y);
            }
        }
        __syncthreads();
        buf ^= 1;
    }

    // ---- write out ----
#pragma unroll
    for (int i = 0; i < 8; i++) {
        int grow = row0 + rt + 16 * i;
        if (grow < R) {
            float a, b, c2, d2;
            upk2(acc[i][0], a, b);
            upk2(acc[i][1], c2, d2);
            *(float4*)(g_z + (size_t)(zRowOffset + grow) * F + 4 * ft) =
                make_float4(a, b, c2, d2);
        }
    }
}

// ============================================================
// edge pass 1: e = leaky_relu(dot(z[src], z[dst])), atomicMax m[dst]
// 2 edges per half-warp (measured optimum), front-batched gathers.
// ============================================================
__global__ __launch_bounds__(256) void edge_score_kernel(
    const int* __restrict__ src, const int* __restrict__ dst)
{
    int lane = threadIdx.x & 31;
    int half = lane >> 4;
    int l16  = lane & 15;
    int warp = (blockIdx.x * (blockDim.x >> 5)) + (threadIdx.x >> 5);
    int e0 = warp * 4 + half * 2;   // edges e0, e0+1

    int2 s = *(const int2*)(src + e0);
    int2 d = *(const int2*)(dst + e0);

    float4 a0 = ((const float4*)(g_z + (size_t)s.x * F))[l16];
    float4 b0 = ((const float4*)(g_z + (size_t)d.x * F))[l16];
    float4 a1 = ((const float4*)(g_z + (size_t)s.y * F))[l16];
    float4 b1 = ((const float4*)(g_z + (size_t)d.y * F))[l16];

    float p0 = a0.x * b0.x + a0.y * b0.y + a0.z * b0.z + a0.w * b0.w;
    float p1 = a1.x * b1.x + a1.y * b1.y + a1.z * b1.z + a1.w * b1.w;
#pragma unroll
    for (int off = 8; off >= 1; off >>= 1) {
        p0 += __shfl_xor_sync(0xffffffffu, p0, off);
        p1 += __shfl_xor_sync(0xffffffffu, p1, off);
    }
    if (l16 == 0) {
        float v0 = (p0 >= 0.f) ? p0 : SLOPE * p0;
        float v1 = (p1 >= 0.f) ? p1 : SLOPE * p1;
        *(float2*)(g_e + e0) = make_float2(v0, v1);
        unsigned k0 = __float_as_uint(v0); k0 = (k0 & 0x80000000u) ? ~k0 : (k0 | 0x80000000u);
        unsigned k1 = __float_as_uint(v1); k1 = (k1 & 0x80000000u) ? ~k1 : (k1 | 0x80000000u);
        atomicMax(&g_mkey[d.x], k0);
        atomicMax(&g_mkey[d.y], k1);
    }
}

// ============================================================
// edge pass 2 (fused exp + scatter, deferred normalization):
//   ex = exp(e - m[dst]);  den[dst] += ex;  h[dst] += ex * z[src]
// 2 edges per half-warp; exp on one lane, shfl broadcast.
// ============================================================
__global__ __launch_bounds__(256) void edge_accum_kernel(
    const int* __restrict__ src, const int* __restrict__ dst)
{
    int lane = threadIdx.x & 31;
    int half = lane >> 4;
    int l16  = lane & 15;
    int warp = (blockIdx.x * (blockDim.x >> 5)) + (threadIdx.x >> 5);
    int e0 = warp * 4 + half * 2;

    int2 s = *(const int2*)(src + e0);
    int2 d = *(const int2*)(dst + e0);

    float4 a0 = ((const float4*)(g_z + (size_t)s.x * F))[l16];
    float4 a1 = ((const float4*)(g_z + (size_t)s.y * F))[l16];

    float ex0 = 0.f, ex1 = 0.f;
    if (l16 == 0) {
        float2 ge = *(const float2*)(g_e + e0);
        unsigned k0 = g_mkey[d.x], k1 = g_mkey[d.y];
        float m0 = __uint_as_float((k0 & 0x80000000u) ? (k0 & 0x7fffffffu) : ~k0);
        float m1 = __uint_as_float((k1 & 0x80000000u) ? (k1 & 0x7fffffffu) : ~k1);
        ex0 = expf(ge.x - m0);
        ex1 = expf(ge.y - m1);
        atomicAdd(&g_den[d.x], ex0);
        atomicAdd(&g_den[d.y], ex1);
    }
    int srcLane = half << 4;
    ex0 = __shfl_sync(0xffffffffu, ex0, srcLane);
    ex1 = __shfl_sync(0xffffffffu, ex1, srcLane);

    float* hp0 = g_h + (size_t)d.x * F + l16 * 4;
    float* hp1 = g_h + (size_t)d.y * F + l16 * 4;
    asm volatile("red.global.add.v4.f32 [%0], {%1, %2, %3, %4};"
                 :: "l"(hp0), "f"(a0.x * ex0), "f"(a0.y * ex0), "f"(a0.z * ex0), "f"(a0.w * ex0)
                 : "memory");
    asm volatile("red.global.add.v4.f32 [%0], {%1, %2, %3, %4};"
                 :: "l"(hp1), "f"(a1.x * ex1), "f"(a1.y * ex1), "f"(a1.z * ex1), "f"(a1.w * ex1)
                 : "memory");
}

// ============================================================
// denom -> reciprocal (0 for empty nodes)
// ============================================================
__global__ void rden_kernel() {
    int i = blockIdx.x * blockDim.x + threadIdx.x;
    if (i < N_NODES) {
        float d = g_den[i];
        g_den[i] = (d > 0.f) ? (1.f / d) : 0.f;
    }
}

// ============================================================
// finalize: out = elu(h * rden[node])
// ============================================================
__global__ void finalize_kernel(float* __restrict__ out) {
    int i = blockIdx.x * blockDim.x + threadIdx.x;
    if (i < N_NODES * F) {
        float x = g_h[i] * g_den[i >> 6];
        out[i] = (x > 0.f) ? x : expm1f(x);
    }
}

// ============================================================
extern "C" void kernel_launch(void* const* d_in, const int* in_sizes, int n_in,
                              void* d_out, int out_size) {
    const float* d_sim  = (const float*)d_in[0];
    const float* mi_sim = (const float*)d_in[1];
    const float* W_d    = (const float*)d_in[2];
    const float* W_mi   = (const float*)d_in[3];
    const int*   src    = (const int*)d_in[4];
    const int*   dst    = (const int*)d_in[5];
    float* out = (float*)d_out;

    cudaFuncSetAttribute(gemm_kernel, cudaFuncAttributeMaxDynamicSharedMemorySize,
                         GEMM_SMEM_BYTES);

    init_kernel<<<(N_NODES * F + 255) / 256, 256>>>();

    gemm_kernel<<<NB_D + NB_M, 256, GEMM_SMEM_BYTES>>>(d_sim, W_d, mi_sim, W_mi);

    // 4 edges per warp, 8 warps per block -> 32 edges per block
    edge_score_kernel<<<N_EDGES / 32, 256>>>(src, dst);
    edge_accum_kernel<<<N_EDGES / 32, 256>>>(src, dst);
    rden_kernel<<<(N_NODES + 255) / 256, 256>>>();
    finalize_kernel<<<(N_NODES * F + 255) / 256, 256>>>(out);
}